// round 6
// baseline (speedup 1.0000x reference)
#include <cuda_runtime.h>
#include <math.h>

#define N_NODES  50000
#define N_EDGES  400000
#define NCH      16
#define RCUT     10.0f
#define MAX_DEG  64
#define TOTAL_NK (N_NODES * NCH)            // 800000
#define TOTAL_EK (N_EDGES * NCH)            // 6400000
#define OUT1_OFF (N_NODES * NCH)            // 800000
#define OUT2_OFF (N_NODES * NCH * 4)        // 3200000

// ---- scratch (__device__ globals: no allocation allowed) ----
__device__ float  g_dist[N_EDGES];
__device__ int    g_cnt[N_NODES];                 // degree by src (zero at entry, reset by gather)
__device__ float4 g_rec4[N_NODES * MAX_DEG];      // (ux,uy,uz, dst-as-bits) bucketed by src
__device__ int    g_rece[N_NODES * MAX_DEG];      // original edge id per slot
__device__ float  g_rho[TOTAL_EK];                // rho[e*16+k], linear & coalesced
__device__ float4 g_hpack[TOTAL_NK * 4];          // packed {s,v,M,pad} per (node,channel), 64B

// geometry + direct bucket scatter of edge records
__global__ void geom_kernel(const float* __restrict__ pos,
                            const int* __restrict__ ei) {
    int e = blockIdx.x * blockDim.x + threadIdx.x;
    if (e >= N_EDGES) return;
    int s = ei[e];
    int d = ei[N_EDGES + e];
    float rx = pos[3 * s + 0] - pos[3 * d + 0];
    float ry = pos[3 * s + 1] - pos[3 * d + 1];
    float rz = pos[3 * s + 2] - pos[3 * d + 2];
    float d2 = rx * rx + ry * ry + rz * rz;
    float inv = rsqrtf(d2);
    g_dist[e] = d2 * inv;
    int rank = atomicAdd(&g_cnt[s], 1);
    int slot = s * MAX_DEG + rank;
    g_rec4[slot] = make_float4(rx * inv, ry * inv, rz * inv, __int_as_float(d));
    g_rece[slot] = e;
}

// radial basis with faithful [K,E]->[E,K] reshape quirk; linear coalesced store
__global__ void rho_kernel() {
    int idx = blockIdx.x * blockDim.x + threadIdx.x;
    if (idx >= TOTAL_EK) return;
    int n_idx = idx / N_EDGES;
    int e_idx = idx - n_idx * N_EDGES;
    float rr  = g_dist[e_idx];
    g_rho[idx] = 0.44721359549995794f *
                 __sinf((float)(n_idx + 1) * ((float)M_PI / RCUT) * rr) / rr;
}

// repack h0/h1/h2 into one 64B record per (node,channel):
// {s, vx, vy, vz, M00, M01, M02, M10, M11, M12, M20, M21, M22, 0, 0, 0}
__global__ void pack_kernel(const float* __restrict__ h0,
                            const float* __restrict__ h1,
                            const float* __restrict__ h2) {
    int idx = blockIdx.x * blockDim.x + threadIdx.x;
    if (idx >= TOTAL_NK) return;
    const float* vp = h1 + (size_t)idx * 3;
    const float* Mp = h2 + (size_t)idx * 9;
    float4* o = g_hpack + (size_t)idx * 4;
    o[0] = make_float4(h0[idx], vp[0], vp[1], vp[2]);
    o[1] = make_float4(Mp[0], Mp[1], Mp[2], Mp[3]);
    o[2] = make_float4(Mp[4], Mp[5], Mp[6], Mp[7]);
    o[3] = make_float4(Mp[8], 0.0f, 0.0f, 0.0f);
}

// gather-reduce: one thread per (node, channel). Writes every output once.
__global__ void __launch_bounds__(256)
gather_kernel(float* __restrict__ out) {
    int idx = blockIdx.x * blockDim.x + threadIdx.x;
    if (idx >= TOTAL_NK) return;
    int n = idx >> 4;
    int k = idx & 15;

    int cnt = g_cnt[n];
    int off = n * MAX_DEG;

    float a0 = 0.0f;
    float a1x = 0.0f, a1y = 0.0f, a1z = 0.0f;
    float a2[9] = {0,0,0,0,0,0,0,0,0};

    #pragma unroll 2
    for (int j = 0; j < cnt; ++j) {
        float4 rec = g_rec4[off + j];          // broadcast across 16 k-lanes
        int    e   = g_rece[off + j];          // broadcast
        float  rho = __ldg(g_rho + e * NCH + k);  // 64B contiguous per edge

        float ux = rec.x, uy = rec.y, uz = rec.z;
        int dst  = __float_as_int(rec.w);
        const float4* hp = g_hpack + (size_t)(dst * NCH + k) * 4;  // 1KB/edge, coalesced

        float4 A = __ldg(hp + 0);
        float4 B = __ldg(hp + 1);
        float4 C = __ldg(hp + 2);
        float4 D = __ldg(hp + 3);

        float s = A.x, vx = A.y, vy = A.z, vz = A.w;
        float M00 = B.x, M01 = B.y, M02 = B.z, M10 = B.w;
        float M11 = C.x, M12 = C.y, M20 = C.z, M21 = C.w;
        float M22 = D.x;

        float vd = vx * ux + vy * uy + vz * uz;
        float tr = M00 + M11 + M22;
        float Mux  = M00 * ux + M01 * uy + M02 * uz;
        float Muy  = M10 * ux + M11 * uy + M12 * uz;
        float Muz  = M20 * ux + M21 * uy + M22 * uz;
        float Mtux = M00 * ux + M10 * uy + M20 * uz;
        float Mtuy = M01 * ux + M11 * uy + M21 * uz;
        float Mtuz = M02 * ux + M12 * uy + M22 * uz;
        float uMu  = ux * Mux + uy * Muy + uz * Muz;

        // out0
        a0 += rho * (2.0f * s + vd + 2.0f * tr + 2.0f * uMu);

        // out1 = rho*( (s + 2*vd + tr)*u + 2*v + (M+Mt)u )
        float c1 = rho * (s + 2.0f * vd + tr);
        a1x += c1 * ux + rho * (2.0f * vx + Mux + Mtux);
        a1y += c1 * uy + rho * (2.0f * vy + Muy + Mtuy);
        a1z += c1 * uz + rho * (2.0f * vz + Muz + Mtuz);

        // out2 = 2*rho*M + a (x) u ; a = rho*((s+tr)*u + v + 2*(Mu+Mtu))
        float ct = rho * (s + tr);
        float ax = ct * ux + rho * (vx + 2.0f * (Mux + Mtux));
        float ay = ct * uy + rho * (vy + 2.0f * (Muy + Mtuy));
        float az = ct * uz + rho * (vz + 2.0f * (Muz + Mtuz));
        float r2m = 2.0f * rho;
        a2[0] += r2m * M00 + ax * ux;
        a2[1] += r2m * M01 + ax * uy;
        a2[2] += r2m * M02 + ax * uz;
        a2[3] += r2m * M10 + ay * ux;
        a2[4] += r2m * M11 + ay * uy;
        a2[5] += r2m * M12 + ay * uz;
        a2[6] += r2m * M20 + az * ux;
        a2[7] += r2m * M21 + az * uy;
        a2[8] += r2m * M22 + az * uz;
    }

    out[idx] = a0;
    float* o1 = out + OUT1_OFF + (size_t)idx * 3;
    o1[0] = a1x; o1[1] = a1y; o1[2] = a1z;
    float* o2 = out + OUT2_OFF + (size_t)idx * 9;
    #pragma unroll
    for (int j = 0; j < 9; ++j) o2[j] = a2[j];

    // reset degree counter for next launch (all 16 k-lanes of node n share a warp)
    if (k == 0) g_cnt[n] = 0;
}

extern "C" void kernel_launch(void* const* d_in, const int* in_sizes, int n_in,
                              void* d_out, int out_size) {
    const float* h0  = (const float*)d_in[0];
    const float* h1  = (const float*)d_in[1];
    const float* h2  = (const float*)d_in[2];
    const float* pos = (const float*)d_in[3];
    // d_in[4] = channel_weights (provably unused by reference output)
    const int*   ei  = (const int*)d_in[5];
    float* out = (float*)d_out;

    geom_kernel<<<(N_EDGES + 255) / 256, 256>>>(pos, ei);
    rho_kernel<<<(TOTAL_EK + 255) / 256, 256>>>();
    pack_kernel<<<(TOTAL_NK + 255) / 256, 256>>>(h0, h1, h2);
    gather_kernel<<<(TOTAL_NK + 255) / 256, 256>>>(out);
}

// round 7
// speedup vs baseline: 1.1438x; 1.1438x over previous
#include <cuda_runtime.h>
#include <math.h>

#define N_NODES  50000
#define N_EDGES  400000
#define NCH      16
#define RCUT     10.0f
#define MAX_DEG  64
#define TOTAL_NK (N_NODES * NCH)            // 800000 = 3125*256 exactly
#define OUT1_OFF (N_NODES * NCH)            // 800000
#define OUT2_OFF (N_NODES * NCH * 4)        // 3200000

// ---- scratch (__device__ globals: no allocation allowed) ----
__device__ float  g_dist[N_EDGES];
__device__ int    g_cnt[N_NODES];                 // degree by src (zero at entry, reset by gather)
__device__ float4 g_rec4[N_NODES * MAX_DEG];      // (ux,uy,uz, dst-as-bits) bucketed by src
__device__ int    g_rece[N_NODES * MAX_DEG];      // original edge id per slot

// geometry + direct bucket scatter of edge records
__global__ void geom_kernel(const float* __restrict__ pos,
                            const int* __restrict__ ei) {
    int e = blockIdx.x * blockDim.x + threadIdx.x;
    if (e >= N_EDGES) return;
    int s = ei[e];
    int d = ei[N_EDGES + e];
    float rx = pos[3 * s + 0] - pos[3 * d + 0];
    float ry = pos[3 * s + 1] - pos[3 * d + 1];
    float rz = pos[3 * s + 2] - pos[3 * d + 2];
    float d2 = rx * rx + ry * ry + rz * rz;
    float inv = rsqrtf(d2);
    g_dist[e] = d2 * inv;
    int rank = atomicAdd(&g_cnt[s], 1);
    int slot = s * MAX_DEG + rank;
    g_rec4[slot] = make_float4(rx * inv, ry * inv, rz * inv, __int_as_float(d));
    g_rece[slot] = e;
}

// gather-reduce with warp-cooperative staging of h rows through shared memory.
// One thread per (node, channel); half-warp (16 lanes) = one node.
__global__ void __launch_bounds__(256)
gather_kernel(const float* __restrict__ h0,
              const float* __restrict__ h1,
              const float* __restrict__ h2,
              float* __restrict__ out) {
    // 8 warps * 2 nodes * 52 float4 (832B per node)
    __shared__ float4 sh[8 * 104];

    int idx = blockIdx.x * blockDim.x + threadIdx.x;   // grid covers exactly TOTAL_NK
    int n = idx >> 4;
    int k = idx & 15;
    int warpid = threadIdx.x >> 5;
    int half   = (threadIdx.x >> 4) & 1;

    int cnt = g_cnt[n];
    int off = n * MAX_DEG;

    // warp loop bound = max degree of the warp's two nodes
    int ocnt = __shfl_xor_sync(0xffffffffu, cnt, 16);
    int cmax = max(cnt, ocnt);

    float4* reg = sh + warpid * 104 + half * 52;       // this node's staging region
    const float* smf = (const float*)(sh) + warpid * 416 + half * 208;

    float a0 = 0.0f;
    float a1x = 0.0f, a1y = 0.0f, a1z = 0.0f;
    float a2[9] = {0,0,0,0,0,0,0,0,0};

    for (int j = 0; j < cmax; ++j) {
        bool valid = (j < cnt);
        int jj = valid ? j : 0;

        float4 rec = g_rec4[off + jj];                 // broadcast within half-warp
        int    e   = g_rece[off + jj];

        int dst = valid ? __float_as_int(rec.w) : 0;
        float ux = rec.x, uy = rec.y, uz = rec.z;

        // radial (faithful [K,E]->[E,K] reshape quirk); rho=0 kills invalid lanes
        int flat  = e * NCH + k;
        int n_idx = flat / N_EDGES;
        int e_idx = flat - n_idx * N_EDGES;
        float rr  = g_dist[e_idx];
        float rho = valid ? (0.44721359549995794f *
                    __sinf((float)(n_idx + 1) * ((float)M_PI / RCUT) * rr) / rr)
                          : 0.0f;

        // ---- cooperative coalesced load: 52 float4 = 832B per node ----
        const float4* H0 = (const float4*)(h0 + (size_t)dst * 16);   // 4 f4
        const float4* H1 = (const float4*)(h1 + (size_t)dst * 48);   // 12 f4
        const float4* H2 = (const float4*)(h2 + (size_t)dst * 144);  // 36 f4
        if (k < 4) reg[k]      = __ldg(H0 + k);
        else       reg[k]      = __ldg(H1 + (k - 4));
        if (k < 8) reg[8 + k]  = __ldg(H1 + (4 + k));
        reg[16 + k] = __ldg(H2 + k);
        reg[32 + k] = __ldg(H2 + 16 + k);
        if (k < 4) reg[48 + k] = __ldg(H2 + 32 + k);
        __syncwarp();

        // ---- per-channel reads from smem (bank-conflict-free strides 1/3/9) ----
        float s  = smf[k];
        float vx = smf[16 + 3 * k], vy = smf[17 + 3 * k], vz = smf[18 + 3 * k];
        const float* Mp = smf + 64 + 9 * k;
        float M00 = Mp[0], M01 = Mp[1], M02 = Mp[2];
        float M10 = Mp[3], M11 = Mp[4], M12 = Mp[5];
        float M20 = Mp[6], M21 = Mp[7], M22 = Mp[8];

        float vd = vx * ux + vy * uy + vz * uz;
        float tr = M00 + M11 + M22;
        float Mux  = M00 * ux + M01 * uy + M02 * uz;
        float Muy  = M10 * ux + M11 * uy + M12 * uz;
        float Muz  = M20 * ux + M21 * uy + M22 * uz;
        float Mtux = M00 * ux + M10 * uy + M20 * uz;
        float Mtuy = M01 * ux + M11 * uy + M21 * uz;
        float Mtuz = M02 * ux + M12 * uy + M22 * uz;
        float uMu  = ux * Mux + uy * Muy + uz * Muz;

        // out0
        a0 += rho * (2.0f * s + vd + 2.0f * tr + 2.0f * uMu);

        // out1 = rho*( (s + 2*vd + tr)*u + 2*v + (M+Mt)u )
        float c1 = rho * (s + 2.0f * vd + tr);
        a1x += c1 * ux + rho * (2.0f * vx + Mux + Mtux);
        a1y += c1 * uy + rho * (2.0f * vy + Muy + Mtuy);
        a1z += c1 * uz + rho * (2.0f * vz + Muz + Mtuz);

        // out2 = 2*rho*M + a (x) u ; a = rho*((s+tr)*u + v + 2*(Mu+Mtu))
        float ct = rho * (s + tr);
        float ax = ct * ux + rho * (vx + 2.0f * (Mux + Mtux));
        float ay = ct * uy + rho * (vy + 2.0f * (Muy + Mtuy));
        float az = ct * uz + rho * (vz + 2.0f * (Muz + Mtuz));
        float r2m = 2.0f * rho;
        a2[0] += r2m * M00 + ax * ux;
        a2[1] += r2m * M01 + ax * uy;
        a2[2] += r2m * M02 + ax * uz;
        a2[3] += r2m * M10 + ay * ux;
        a2[4] += r2m * M11 + ay * uy;
        a2[5] += r2m * M12 + ay * uz;
        a2[6] += r2m * M20 + az * ux;
        a2[7] += r2m * M21 + az * uy;
        a2[8] += r2m * M22 + az * uz;

        __syncwarp();   // staging buffer reusable next iteration
    }

    out[idx] = a0;
    float* o1 = out + OUT1_OFF + (size_t)idx * 3;
    o1[0] = a1x; o1[1] = a1y; o1[2] = a1z;
    float* o2 = out + OUT2_OFF + (size_t)idx * 9;
    #pragma unroll
    for (int j = 0; j < 9; ++j) o2[j] = a2[j];

    // reset degree counter for next launch (all 16 k-lanes of node n share a warp)
    if (k == 0) g_cnt[n] = 0;
}

extern "C" void kernel_launch(void* const* d_in, const int* in_sizes, int n_in,
                              void* d_out, int out_size) {
    const float* h0  = (const float*)d_in[0];
    const float* h1  = (const float*)d_in[1];
    const float* h2  = (const float*)d_in[2];
    const float* pos = (const float*)d_in[3];
    // d_in[4] = channel_weights (provably unused by reference output)
    const int*   ei  = (const int*)d_in[5];
    float* out = (float*)d_out;

    geom_kernel<<<(N_EDGES + 255) / 256, 256>>>(pos, ei);
    gather_kernel<<<(TOTAL_NK + 255) / 256, 256>>>(h0, h1, h2, out);
}

// round 8
// speedup vs baseline: 1.5038x; 1.3148x over previous
#include <cuda_runtime.h>
#include <math.h>

#define N_NODES  50000
#define N_EDGES  400000
#define NCH      16
#define RCUT     10.0f
#define MAX_DEG  64
#define OUT1_OFF (N_NODES * NCH)            // 800000
#define OUT2_OFF (N_NODES * NCH * 4)        // 3200000
#define WPB      8                          // warps (=nodes) per block

// ---- scratch (__device__ globals: no allocation allowed) ----
__device__ float  g_dist[N_EDGES];
__device__ int    g_cnt[N_NODES];                 // degree by src (zero at entry, reset by gather)
__device__ float4 g_rec4[N_NODES * MAX_DEG];      // (ux,uy,uz, dst-as-bits) bucketed by src
__device__ int    g_rece[N_NODES * MAX_DEG];      // original edge id per slot

// geometry + direct bucket scatter of edge records
__global__ void geom_kernel(const float* __restrict__ pos,
                            const int* __restrict__ ei) {
    int e = blockIdx.x * blockDim.x + threadIdx.x;
    if (e >= N_EDGES) return;
    int s = ei[e];
    int d = ei[N_EDGES + e];
    float rx = pos[3 * s + 0] - pos[3 * d + 0];
    float ry = pos[3 * s + 1] - pos[3 * d + 1];
    float rz = pos[3 * s + 2] - pos[3 * d + 2];
    float d2 = rx * rx + ry * ry + rz * rz;
    float inv = rsqrtf(d2);
    g_dist[e] = d2 * inv;
    int rank = atomicAdd(&g_cnt[s], 1);
    int slot = s * MAX_DEG + rank;
    g_rec4[slot] = make_float4(rx * inv, ry * inv, rz * inv, __int_as_float(d));
    g_rece[slot] = e;
}

// gather: ONE WARP PER NODE. Half-warp h processes edges 2j+h; lanes k=0..15
// are channels. h rows staged via smem (52 float4 per edge, conflict-free).
__global__ void __launch_bounds__(256)
gather_kernel(const float* __restrict__ h0,
              const float* __restrict__ h1,
              const float* __restrict__ h2,
              float* __restrict__ out) {
    __shared__ float4 sh[WPB * 104];       // 2 edges * 52 f4 per warp

    int warpid = threadIdx.x >> 5;
    int lane   = threadIdx.x & 31;
    int half   = lane >> 4;
    int k      = lane & 15;
    int n      = blockIdx.x * WPB + warpid;   // grid covers exactly N_NODES

    int cnt = g_cnt[n];
    int off = n * MAX_DEG;

    float4* stg = sh + warpid * 104 + half * 52;
    const float* smf = (const float*)(sh + warpid * 104) + half * 208;

    float a0 = 0.0f;
    float a1x = 0.0f, a1y = 0.0f, a1z = 0.0f;
    float a2[9] = {0,0,0,0,0,0,0,0,0};

    int jmax = (cnt + 1) >> 1;
    for (int j = 0; j < jmax; ++j) {
        int idx2 = 2 * j + half;
        bool valid = idx2 < cnt;
        int slot = off + (valid ? idx2 : 0);

        float4 rec = g_rec4[slot];          // broadcast within half-warp
        int    e   = g_rece[slot];
        int dst = __float_as_int(rec.w);
        float ux = rec.x, uy = rec.y, uz = rec.z;

        // inline radial (faithful [K,E]->[E,K] reshape quirk); rho=0 kills invalid half
        int flat  = e * NCH + k;
        int n_idx = flat / N_EDGES;
        int e_idx = flat - n_idx * N_EDGES;
        float rr  = g_dist[e_idx];          // 16 consecutive floats per half-warp
        float rho = valid ? (0.44721359549995794f *
                    __sinf((float)(n_idx + 1) * ((float)M_PI / RCUT) * rr) / rr)
                          : 0.0f;

        // ---- cooperative staging: this half's edge, 52 f4 = 832B ----
        const float4* H0 = (const float4*)(h0 + (size_t)dst * 16);
        const float4* H1 = (const float4*)(h1 + (size_t)dst * 48);
        const float4* H2 = (const float4*)(h2 + (size_t)dst * 144);
        stg[k]      = __ldg(k < 4 ? H0 + k : H1 + (k - 4));
        stg[16 + k] = __ldg(H2 + k);
        stg[32 + k] = __ldg(H2 + 16 + k);
        if (k < 4) stg[48 + k] = __ldg(H2 + 32 + k);
        __syncwarp();

        // ---- per-channel smem reads (bank-conflict-free, incl. across halves) ----
        float s  = smf[k];
        float vx = smf[16 + 3 * k], vy = smf[17 + 3 * k], vz = smf[18 + 3 * k];
        const float* Mp = smf + 64 + 9 * k;
        float M00 = Mp[0], M01 = Mp[1], M02 = Mp[2];
        float M10 = Mp[3], M11 = Mp[4], M12 = Mp[5];
        float M20 = Mp[6], M21 = Mp[7], M22 = Mp[8];

        float vd = vx * ux + vy * uy + vz * uz;
        float tr = M00 + M11 + M22;
        float Mux  = M00 * ux + M01 * uy + M02 * uz;
        float Muy  = M10 * ux + M11 * uy + M12 * uz;
        float Muz  = M20 * ux + M21 * uy + M22 * uz;
        float Mtux = M00 * ux + M10 * uy + M20 * uz;
        float Mtuy = M01 * ux + M11 * uy + M21 * uz;
        float Mtuz = M02 * ux + M12 * uy + M22 * uz;
        float uMu  = ux * Mux + uy * Muy + uz * Muz;

        a0 += rho * (2.0f * s + vd + 2.0f * tr + 2.0f * uMu);

        float c1 = rho * (s + 2.0f * vd + tr);
        a1x += c1 * ux + rho * (2.0f * vx + Mux + Mtux);
        a1y += c1 * uy + rho * (2.0f * vy + Muy + Mtuy);
        a1z += c1 * uz + rho * (2.0f * vz + Muz + Mtuz);

        float ct = rho * (s + tr);
        float ax = ct * ux + rho * (vx + 2.0f * (Mux + Mtux));
        float ay = ct * uy + rho * (vy + 2.0f * (Muy + Mtuy));
        float az = ct * uz + rho * (vz + 2.0f * (Muz + Mtuz));
        float r2m = 2.0f * rho;
        a2[0] += r2m * M00 + ax * ux;
        a2[1] += r2m * M01 + ax * uy;
        a2[2] += r2m * M02 + ax * uz;
        a2[3] += r2m * M10 + ay * ux;
        a2[4] += r2m * M11 + ay * uy;
        a2[5] += r2m * M12 + ay * uz;
        a2[6] += r2m * M20 + az * ux;
        a2[7] += r2m * M21 + az * uy;
        a2[8] += r2m * M22 + az * uz;

        __syncwarp();                        // staging region reusable
    }

    // ---- merge the two half-warps (channels identical, edges disjoint) ----
    const unsigned FULL = 0xffffffffu;
    a0  += __shfl_xor_sync(FULL, a0, 16);
    a1x += __shfl_xor_sync(FULL, a1x, 16);
    a1y += __shfl_xor_sync(FULL, a1y, 16);
    a1z += __shfl_xor_sync(FULL, a1z, 16);
    #pragma unroll
    for (int j = 0; j < 9; ++j) a2[j] += __shfl_xor_sync(FULL, a2[j], 16);

    // ---- staged output: smem re-layout then coalesced f4 stores ----
    float* w = (float*)(sh + warpid * 104);
    if (half == 0) {
        w[k] = a0;
        w[16 + 3 * k] = a1x; w[17 + 3 * k] = a1y; w[18 + 3 * k] = a1z;
        float* mw = w + 64 + 9 * k;
        #pragma unroll
        for (int j = 0; j < 9; ++j) mw[j] = a2[j];
    }
    __syncwarp();

    const float4* rd = sh + warpid * 104;     // 52 f4 = {out0row, out1row, out2row}
    float4* O0 = (float4*)(out + (size_t)n * 16);
    float4* O1 = (float4*)(out + OUT1_OFF + (size_t)n * 48);
    float4* O2 = (float4*)(out + OUT2_OFF + (size_t)n * 144);
    {
        int t = lane;                          // 0..31
        float4 val = rd[t];
        float4* p = (t < 4) ? (O0 + t) : ((t < 16) ? (O1 + t - 4) : (O2 + t - 16));
        *p = val;
    }
    {
        int t = lane + 32;                     // 32..51
        if (t < 52) O2[t - 16] = rd[t];
    }

    if (lane == 0) g_cnt[n] = 0;               // reset for next launch
}

extern "C" void kernel_launch(void* const* d_in, const int* in_sizes, int n_in,
                              void* d_out, int out_size) {
    const float* h0  = (const float*)d_in[0];
    const float* h1  = (const float*)d_in[1];
    const float* h2  = (const float*)d_in[2];
    const float* pos = (const float*)d_in[3];
    // d_in[4] = channel_weights (provably unused by reference output)
    const int*   ei  = (const int*)d_in[5];
    float* out = (float*)d_out;

    geom_kernel<<<(N_EDGES + 255) / 256, 256>>>(pos, ei);
    gather_kernel<<<N_NODES / WPB, 32 * WPB>>>(h0, h1, h2, out);
}